// round 3
// baseline (speedup 1.0000x reference)
#include <cuda_runtime.h>

// LIF neuron scan, T=16:
//   u1 = mem*0.5 + x[t]*0.5 ; spike = (u1 > 1) ; mem = spike ? 0 : u1
// HBM-bound streaming at the ~6.3 TB/s mixed R/W ceiling. This version:
//  - interleaved t-loop (best measured BW), 2 independent float4 columns
//    per thread for MLP=2 at moderate register cost
//  - exact-wave grid (148*10 CTAs) + grid-stride to kill the tail wave
//  - .cs streaming hints (zero reuse)

#define TSTEPS 16
#define NSM 148
#define CTAS_PER_SM 10
#define THREADS 256

__global__ void __launch_bounds__(THREADS)
lif_scan_kernel(const float* __restrict__ x, float* __restrict__ out, int n_per_step)
{
    const long long total_cols = n_per_step / 4;          // float4 columns: 1,048,576
    const long long half_cols  = total_cols / 2;          // 524,288
    const long long stride4    = total_cols;              // float4 stride between timesteps
    const long long nthreads   = (long long)gridDim.x * blockDim.x;

    const float4* __restrict__ xp = reinterpret_cast<const float4*>(x);
    float4* __restrict__ op = reinterpret_cast<float4*>(out);

    // Each grid-stride iteration handles two columns: c and c + half_cols.
    for (long long c = (long long)blockIdx.x * blockDim.x + threadIdx.x;
         c < half_cols; c += nthreads) {

        const long long c2 = c + half_cols;

        float4 memA = make_float4(0.f, 0.f, 0.f, 0.f);
        float4 memB = make_float4(0.f, 0.f, 0.f, 0.f);

        #pragma unroll
        for (int t = 0; t < TSTEPS; ++t) {
            const long long base = (long long)t * stride4;
            // Two independent 128-bit loads in flight per iteration.
            const float4 a = __ldcs(xp + base + c);
            const float4 b = __ldcs(xp + base + c2);

            float4 sA, sB;

            float u;
            u = fmaf(memA.x, 0.5f, a.x * 0.5f); sA.x = (u > 1.f) ? 1.f : 0.f; memA.x = (u > 1.f) ? 0.f : u;
            u = fmaf(memA.y, 0.5f, a.y * 0.5f); sA.y = (u > 1.f) ? 1.f : 0.f; memA.y = (u > 1.f) ? 0.f : u;
            u = fmaf(memA.z, 0.5f, a.z * 0.5f); sA.z = (u > 1.f) ? 1.f : 0.f; memA.z = (u > 1.f) ? 0.f : u;
            u = fmaf(memA.w, 0.5f, a.w * 0.5f); sA.w = (u > 1.f) ? 1.f : 0.f; memA.w = (u > 1.f) ? 0.f : u;

            u = fmaf(memB.x, 0.5f, b.x * 0.5f); sB.x = (u > 1.f) ? 1.f : 0.f; memB.x = (u > 1.f) ? 0.f : u;
            u = fmaf(memB.y, 0.5f, b.y * 0.5f); sB.y = (u > 1.f) ? 1.f : 0.f; memB.y = (u > 1.f) ? 0.f : u;
            u = fmaf(memB.z, 0.5f, b.z * 0.5f); sB.z = (u > 1.f) ? 1.f : 0.f; memB.z = (u > 1.f) ? 0.f : u;
            u = fmaf(memB.w, 0.5f, b.w * 0.5f); sB.w = (u > 1.f) ? 1.f : 0.f; memB.w = (u > 1.f) ? 0.f : u;

            __stcs(op + base + c,  sA);
            __stcs(op + base + c2, sB);
        }
    }
}

extern "C" void kernel_launch(void* const* d_in, const int* in_sizes, int n_in,
                              void* d_out, int out_size)
{
    const float* x = (const float*)d_in[0];
    float* out = (float*)d_out;

    int total = in_sizes[0];
    int n_per_step = total / TSTEPS;          // 4,194,304

    int blocks = NSM * CTAS_PER_SM;           // 1480 CTAs — exact waves, grid-stride
    lif_scan_kernel<<<blocks, THREADS>>>(x, out, n_per_step);
}

// round 4
// speedup vs baseline: 1.2869x; 1.2869x over previous
#include <cuda_runtime.h>

// LIF neuron scan, T=16:
//   u1 = mem*0.5 + x[t]*0.5 ; spike = (u1 > 1) ; mem = spike ? 0 : u1
// HBM-bound streaming (512 MB compulsory traffic, 1:1 R/W mix) at the
// ~6.3 TB/s mixed ceiling. Operating point learned from R1-R3:
//   - 1 float4 column per thread, interleaved t-loop  (best measured BW)
//   - regs <= 32 so occupancy stays ~86% (warp count supplies the MLP;
//     per-thread MLP batching was neutral (R2), occupancy loss fatal (R3))
//   - pure 32-bit indexing (all offsets < 2^31), exact grid, no guard

#define TSTEPS 16

__global__ void __launch_bounds__(256)
lif_scan_kernel(const float* __restrict__ x, float* __restrict__ out)
{
    // Exactly 1,048,576 float4 columns; grid is sized to cover them exactly.
    const unsigned col = blockIdx.x * 256u + threadIdx.x;           // 0 .. 2^20-1
    const unsigned stride4 = 1u << 20;                              // float4 cols per timestep

    const float4* __restrict__ xp = reinterpret_cast<const float4*>(x) + col;
    float4* __restrict__ op = reinterpret_cast<float4*>(out) + col;

    float4 mem = make_float4(0.f, 0.f, 0.f, 0.f);

    #pragma unroll
    for (int t = 0; t < TSTEPS; ++t) {
        const unsigned off = (unsigned)t * stride4;
        const float4 xt = xp[off];

        float4 s;
        float u;
        u = fmaf(mem.x, 0.5f, xt.x * 0.5f); s.x = (u > 1.f) ? 1.f : 0.f; mem.x = (u > 1.f) ? 0.f : u;
        u = fmaf(mem.y, 0.5f, xt.y * 0.5f); s.y = (u > 1.f) ? 1.f : 0.f; mem.y = (u > 1.f) ? 0.f : u;
        u = fmaf(mem.z, 0.5f, xt.z * 0.5f); s.z = (u > 1.f) ? 1.f : 0.f; mem.z = (u > 1.f) ? 0.f : u;
        u = fmaf(mem.w, 0.5f, xt.w * 0.5f); s.w = (u > 1.f) ? 1.f : 0.f; mem.w = (u > 1.f) ? 0.f : u;

        op[off] = s;
    }
}

extern "C" void kernel_launch(void* const* d_in, const int* in_sizes, int n_in,
                              void* d_out, int out_size)
{
    const float* x = (const float*)d_in[0];
    float* out = (float*)d_out;

    // 67,108,864 elements / 16 timesteps / 4 per float4 / 256 threads = 4096 CTAs exactly.
    lif_scan_kernel<<<4096, 256>>>(x, out);
}